// round 10
// baseline (speedup 1.0000x reference)
#include <cuda_runtime.h>
#include <cuda_bf16.h>
#include <mma.h>
#include <math.h>
#include <float.h>
#include <stdint.h>

using namespace nvcuda;

#define Bb_ 2
#define Ss_ 2048
#define Dd_ 1024
#define Hh_ 16
#define HD_ 64
#define Mm_ (Bb_*Ss_)      /* 4096 */
#define NQKV_ (3*Dd_)      /* 3072 */

// ---------------------------------------------------------------------------
// Single scratch arena (80 MB — proven-safe), lifetime-overlapped:
//   [0,16M)   xh/xl (bf16)  -> reused as AOh/AOl after attention
//   [16,28M)  Wqh/Wql       [28,32M) Woh/Wol
//   [32,80M)  Qh,Ql,Kh,Kl,Vh,Vl (bf16 hi/lo, [b,h,s,hd], 8MB each)
// ---------------------------------------------------------------------------
#define MB_ (1024*1024)
__device__ __align__(128) unsigned char g_arena[80*MB_];

#define P_XH  ((__nv_bfloat16*)(g_arena))
#define P_XL  ((__nv_bfloat16*)(g_arena + 8*MB_))
#define P_AOH P_XH
#define P_AOL P_XL
#define P_WQH ((__nv_bfloat16*)(g_arena + 16*MB_))
#define P_WQL ((__nv_bfloat16*)(g_arena + 22*MB_))
#define P_WOH ((__nv_bfloat16*)(g_arena + 28*MB_))
#define P_WOL ((__nv_bfloat16*)(g_arena + 30*MB_))
#define P_QH  ((__nv_bfloat16*)(g_arena + 32*MB_))
#define P_QL  ((__nv_bfloat16*)(g_arena + 40*MB_))
#define P_KH  ((__nv_bfloat16*)(g_arena + 48*MB_))
#define P_KL  ((__nv_bfloat16*)(g_arena + 56*MB_))
#define P_VH  ((__nv_bfloat16*)(g_arena + 64*MB_))
#define P_VL  ((__nv_bfloat16*)(g_arena + 72*MB_))

// ---------------------------------------------------------------------------
// helpers
// ---------------------------------------------------------------------------
__device__ __forceinline__ uint32_t smem_u32(const void* p) {
    uint32_t a;
    asm("{ .reg .u64 t; cvta.to.shared.u64 t, %1; cvt.u32.u64 %0, t; }"
        : "=r"(a) : "l"(p));
    return a;
}
__device__ __forceinline__ void cp16(uint32_t saddr, const void* gaddr) {
    asm volatile("cp.async.cg.shared.global [%0], [%1], 16;"
                 :: "r"(saddr), "l"(gaddr));
}
__device__ __forceinline__ void split_bf16(float v, __nv_bfloat16& h, __nv_bfloat16& l) {
    h = __float2bfloat16_rn(v);
    l = __float2bfloat16_rn(v - __bfloat162float(h));
}

// ---------------------------------------------------------------------------
// Split x (fp32) -> bf16 hi/lo
// ---------------------------------------------------------------------------
__global__ __launch_bounds__(256) void split_x(const float* __restrict__ in, int n)
{
    __nv_bfloat16* oh = P_XH;
    __nv_bfloat16* ol = P_XL;
    for (int i = (blockIdx.x * 256 + threadIdx.x) * 4; i < n; i += gridDim.x * 1024) {
        float4 v = *(const float4*)(in + i);
        __nv_bfloat16 h[4], l[4];
        split_bf16(v.x, h[0], l[0]);
        split_bf16(v.y, h[1], l[1]);
        split_bf16(v.z, h[2], l[2]);
        split_bf16(v.w, h[3], l[3]);
        *(uint2*)(oh + i) = *(uint2*)h;
        *(uint2*)(ol + i) = *(uint2*)l;
    }
}

// ---------------------------------------------------------------------------
// Transpose W [R,C] -> bf16 hi/lo [C,R] K-major
// ---------------------------------------------------------------------------
template<int WSEL>
__global__ __launch_bounds__(256) void transpose_split(const float* __restrict__ in,
                                                       int R, int C)
{
    __shared__ float t[32][33];
    __nv_bfloat16* oh = (WSEL == 0) ? P_WQH : P_WOH;
    __nv_bfloat16* ol = (WSEL == 0) ? P_WQL : P_WOL;
    const int c0 = blockIdx.x * 32, r0 = blockIdx.y * 32;
    const int tx = threadIdx.x, ty = threadIdx.y;
    #pragma unroll
    for (int i = 0; i < 32; i += 8)
        t[ty + i][tx] = in[(size_t)(r0 + ty + i) * C + c0 + tx];
    __syncthreads();
    #pragma unroll
    for (int i = 0; i < 32; i += 8) {
        float v = t[tx][ty + i];
        __nv_bfloat16 h, l;
        split_bf16(v, h, l);
        const size_t o = (size_t)(c0 + ty + i) * R + r0 + tx;
        oh[o] = h; ol[o] = l;
    }
}

// ---------------------------------------------------------------------------
// WMMA bf16 3-term GEMM, 512 threads = 16 warps (4x4), warp tile 32x32.
// BM=BN=128, BK=32, cp.async double-buffered (same stages as round 9).
// MODE 0: epilogue splits Q/K/V to bf16 hi/lo (Q pre-scaled by 1/8).
// MODE 1: writes Cout + bias (fp32).
// ---------------------------------------------------------------------------
#define LDT 40
#define MAT_ELEM (128*LDT)
#define MAT_BYTES (MAT_ELEM*2)
#define STAGE_BYTES (4*MAT_BYTES)
#define GEMM_SMEM (2*STAGE_BYTES)

template<int MODE>
__global__ __launch_bounds__(512) void gemm_bf16x3(
    const float* __restrict__ bias, float* __restrict__ Cout)
{
    extern __shared__ __align__(16) char smem[];
    const uint32_t sbase = smem_u32(smem);
    const int tid = threadIdx.x;
    const int wid = tid >> 5, lane = tid & 31;
    const int warp_m = wid >> 2, warp_n = wid & 3;   // 4x4 warps, 32x32 tiles
    const int cCol = blockIdx.x, cRow = blockIdx.y;
    const int Kd = Dd_;

    const __nv_bfloat16* Agh = (MODE == 0) ? P_XH : P_AOH;
    const __nv_bfloat16* Agl = (MODE == 0) ? P_XL : P_AOL;
    const __nv_bfloat16* Bgh = (MODE == 0) ? P_WQH : P_WOH;
    const __nv_bfloat16* Bgl = (MODE == 0) ? P_WQL : P_WOL;

    const __nv_bfloat16* Ah_g = Agh + (size_t)(cRow * 128) * Kd;
    const __nv_bfloat16* Al_g = Agl + (size_t)(cRow * 128) * Kd;
    const __nv_bfloat16* Bh_g = Bgh + (size_t)(cCol * 128) * Kd;
    const __nv_bfloat16* Bl_g = Bgl + (size_t)(cCol * 128) * Kd;

    wmma::fragment<wmma::accumulator, 16, 16, 16, float> acc[2][2];
    #pragma unroll
    for (int i = 0; i < 2; i++)
        #pragma unroll
        for (int j = 0; j < 2; j++)
            wmma::fill_fragment(acc[i][j], 0.0f);

    // stage loader: 512 16B-chunks per matrix, 1 chunk/thread/matrix
    auto issue = [&](int kc) {
        const uint32_t sb = sbase + (kc & 1) * STAGE_BYTES;
        const int row = tid >> 2, c4 = tid & 3;
        const size_t go = (size_t)row * Kd + kc * 32 + c4 * 8;
        const uint32_t so = row * (LDT * 2) + c4 * 16;
        cp16(sb + 0*MAT_BYTES + so, Ah_g + go);
        cp16(sb + 1*MAT_BYTES + so, Al_g + go);
        cp16(sb + 2*MAT_BYTES + so, Bh_g + go);
        cp16(sb + 3*MAT_BYTES + so, Bl_g + go);
        asm volatile("cp.async.commit_group;");
    };

    issue(0);

    for (int kc = 0; kc < Kd / 32; kc++) {
        if (kc + 1 < Kd / 32) issue(kc + 1);
        else asm volatile("cp.async.commit_group;");
        asm volatile("cp.async.wait_group 1;");
        __syncthreads();

        const __nv_bfloat16* As_h = (const __nv_bfloat16*)(smem + (kc & 1) * STAGE_BYTES);
        const __nv_bfloat16* As_l = As_h + MAT_ELEM;
        const __nv_bfloat16* Bs_h = As_h + 2*MAT_ELEM;
        const __nv_bfloat16* Bs_l = As_h + 3*MAT_ELEM;

        #pragma unroll
        for (int ks = 0; ks < 32; ks += 16) {
            wmma::fragment<wmma::matrix_a, 16, 16, 16, __nv_bfloat16, wmma::row_major> ah[2], al[2];
            #pragma unroll
            for (int i = 0; i < 2; i++) {
                const int r = warp_m*32 + i*16;
                wmma::load_matrix_sync(ah[i], &As_h[r*LDT + ks], LDT);
                wmma::load_matrix_sync(al[i], &As_l[r*LDT + ks], LDT);
            }
            #pragma unroll
            for (int j = 0; j < 2; j++) {
                const int n = warp_n*32 + j*16;
                wmma::fragment<wmma::matrix_b, 16, 16, 16, __nv_bfloat16, wmma::col_major> bh_f, bl_f;
                wmma::load_matrix_sync(bh_f, &Bs_h[n*LDT + ks], LDT);
                wmma::load_matrix_sync(bl_f, &Bs_l[n*LDT + ks], LDT);
                #pragma unroll
                for (int i = 0; i < 2; i++) {
                    wmma::mma_sync(acc[i][j], ah[i], bh_f, acc[i][j]);
                    wmma::mma_sync(acc[i][j], ah[i], bl_f, acc[i][j]);
                    wmma::mma_sync(acc[i][j], al[i], bh_f, acc[i][j]);
                }
            }
        }
        __syncthreads();
    }

    // epilogue: stage each 16x16 acc tile through per-warp smem patch
    float* patch = (float*)smem + wid * 256;   // 16 warps x 1KB = 16KB
    #pragma unroll
    for (int i = 0; i < 2; i++) {
        #pragma unroll
        for (int j = 0; j < 2; j++) {
            wmma::store_matrix_sync(patch, acc[i][j], 16, wmma::mem_row_major);
            __syncwarp();
            const int m0 = cRow*128 + warp_m*32 + i*16;
            const int n0 = cCol*128 + warp_n*32 + j*16;
            #pragma unroll
            for (int e = 0; e < 8; e++) {
                const int idx = lane*8 + e;
                const int r = idx >> 4, cn = idx & 15;
                const int m = m0 + r, n = n0 + cn;
                const float val = patch[idx] + bias[n];
                if (MODE == 1) {
                    Cout[(size_t)m * Dd_ + n] = val;
                } else {
                    const int b = m >> 11, sq = m & (Ss_ - 1);
                    const int h = n / 192;
                    const int c = n - h * 192;
                    const size_t base = ((size_t)(b * Hh_ + h) * Ss_ + sq) * HD_;
                    __nv_bfloat16 hh, ll;
                    if (c < 64) {
                        split_bf16(val * 0.125f, hh, ll);   // fold 1/sqrt(hd)
                        P_QH[base + c] = hh; P_QL[base + c] = ll;
                    } else if (c < 128) {
                        split_bf16(val, hh, ll);
                        P_KH[base + c - 64] = hh; P_KL[base + c - 64] = ll;
                    } else {
                        split_bf16(val, hh, ll);
                        P_VH[base + c - 128] = hh; P_VL[base + c - 128] = ll;
                    }
                }
            }
            __syncwarp();
        }
    }
}

// ---------------------------------------------------------------------------
// WMMA causal attention, unnormalized softmax (proven round-9 kernel).
// ---------------------------------------------------------------------------
#define AT_SMEM 91392
#define O_SST 0
#define O_QH 17408
#define O_QL 26624
#define O_KH 35840
#define O_KL 45056
#define O_VH 54272
#define O_VL 63488
#define O_PH 72704
#define O_PL 81920
#define O_LS 91136

__global__ __launch_bounds__(128) void attn_wmma()
{
    extern __shared__ __align__(16) char sm[];
    const uint32_t sb = smem_u32(sm);
    float* Sst = (float*)(sm + O_SST);
    __nv_bfloat16* Qh = (__nv_bfloat16*)(sm + O_QH);
    __nv_bfloat16* Ql = (__nv_bfloat16*)(sm + O_QL);
    __nv_bfloat16* Kh = (__nv_bfloat16*)(sm + O_KH);
    __nv_bfloat16* Kl = (__nv_bfloat16*)(sm + O_KL);
    __nv_bfloat16* Vh = (__nv_bfloat16*)(sm + O_VH);
    __nv_bfloat16* Vl = (__nv_bfloat16*)(sm + O_VL);
    __nv_bfloat16* Ph = (__nv_bfloat16*)(sm + O_PH);
    __nv_bfloat16* Pl = (__nv_bfloat16*)(sm + O_PL);
    float* lsum = (float*)(sm + O_LS);

    const int tid = threadIdx.x;
    const int wid = tid >> 5;
    const int qt  = blockIdx.x;
    const int bh  = blockIdx.y;

    {
        const __nv_bfloat16* QHg = P_QH + ((size_t)bh * Ss_ + qt*64) * HD_;
        const __nv_bfloat16* QLg = P_QL + ((size_t)bh * Ss_ + qt*64) * HD_;
        #pragma unroll
        for (int i = 0; i < 4; i++) {
            const int idx = tid + i*128;
            const int row = idx >> 3, c8 = idx & 7;
            const uint32_t so = row*144 + c8*16;
            const int go = row*64 + c8*8;
            cp16(sb + O_QH + so, QHg + go);
            cp16(sb + O_QL + so, QLg + go);
        }
        asm volatile("cp.async.commit_group;");
    }
    if (tid < 64) lsum[tid] = 0.f;

    wmma::fragment<wmma::accumulator, 16, 16, 16, float> accO[4];
    #pragma unroll
    for (int n = 0; n < 4; n++) wmma::fill_fragment(accO[n], 0.0f);

    const int r0 = wid * 16;

    for (int kt = 0; kt <= qt; kt++) {
        {
            const size_t gb = ((size_t)bh * Ss_ + kt*64) * HD_;
            const __nv_bfloat16* KHg = P_KH + gb;
            const __nv_bfloat16* KLg = P_KL + gb;
            const __nv_bfloat16* VHg = P_VH + gb;
            const __nv_bfloat16* VLg = P_VL + gb;
            #pragma unroll
            for (int i = 0; i < 4; i++) {
                const int idx = tid + i*128;
                const int row = idx >> 3, c8 = idx & 7;
                const uint32_t so = row*144 + c8*16;
                const int go = row*64 + c8*8;
                cp16(sb + O_KH + so, KHg + go);
                cp16(sb + O_KL + so, KLg + go);
                cp16(sb + O_VH + so, VHg + go);
                cp16(sb + O_VL + so, VLg + go);
            }
            asm volatile("cp.async.commit_group;");
        }
        asm volatile("cp.async.wait_group 0;");
        __syncthreads();

        wmma::fragment<wmma::accumulator, 16, 16, 16, float> accS[4];
        #pragma unroll
        for (int n = 0; n < 4; n++) wmma::fill_fragment(accS[n], 0.0f);
        #pragma unroll
        for (int k0 = 0; k0 < 64; k0 += 16) {
            wmma::fragment<wmma::matrix_a, 16, 16, 16, __nv_bfloat16, wmma::row_major> ah, al;
            wmma::load_matrix_sync(ah, &Qh[r0*72 + k0], 72);
            wmma::load_matrix_sync(al, &Ql[r0*72 + k0], 72);
            #pragma unroll
            for (int n = 0; n < 4; n++) {
                wmma::fragment<wmma::matrix_b, 16, 16, 16, __nv_bfloat16, wmma::col_major> bh_f, bl_f;
                wmma::load_matrix_sync(bh_f, &Kh[(n*16)*72 + k0], 72);
                wmma::load_matrix_sync(bl_f, &Kl[(n*16)*72 + k0], 72);
                wmma::mma_sync(accS[n], ah, bh_f, accS[n]);
                wmma::mma_sync(accS[n], ah, bl_f, accS[n]);
                wmma::mma_sync(accS[n], al, bh_f, accS[n]);
            }
        }
        #pragma unroll
        for (int n = 0; n < 4; n++)
            wmma::store_matrix_sync(&Sst[r0*68 + n*16], accS[n], 68, wmma::mem_row_major);
        __syncthreads();

        {
            const int row = tid >> 1, c0 = (tid & 1) * 32;
            const bool diag = (kt == qt);
            float partial = 0.f;
            #pragma unroll 8
            for (int c = 0; c < 32; c++) {
                const int col = c0 + c;
                const float s = Sst[row*68 + col];
                const float p = (!diag || col <= row) ? __expf(s) : 0.f;
                partial += p;
                __nv_bfloat16 hh, ll;
                split_bf16(p, hh, ll);
                Ph[row*72 + col] = hh;
                Pl[row*72 + col] = ll;
            }
            const float other = __shfl_xor_sync(0xffffffffu, partial, 1);
            if (!(tid & 1)) lsum[row] += partial + other;
        }
        __syncthreads();

        #pragma unroll
        for (int k0 = 0; k0 < 64; k0 += 16) {
            wmma::fragment<wmma::matrix_a, 16, 16, 16, __nv_bfloat16, wmma::row_major> pa, pal;
            wmma::load_matrix_sync(pa,  &Ph[r0*72 + k0], 72);
            wmma::load_matrix_sync(pal, &Pl[r0*72 + k0], 72);
            #pragma unroll
            for (int n = 0; n < 4; n++) {
                wmma::fragment<wmma::matrix_b, 16, 16, 16, __nv_bfloat16, wmma::row_major> vb, vbl;
                wmma::load_matrix_sync(vb,  &Vh[k0*72 + n*16], 72);
                wmma::load_matrix_sync(vbl, &Vl[k0*72 + n*16], 72);
                wmma::mma_sync(accO[n], pa, vb,  accO[n]);
                wmma::mma_sync(accO[n], pa, vbl, accO[n]);
                wmma::mma_sync(accO[n], pal, vb, accO[n]);
            }
        }
        __syncthreads();
    }

    #pragma unroll
    for (int n = 0; n < 4; n++)
        wmma::store_matrix_sync(&Sst[r0*68 + n*16], accO[n], 68, wmma::mem_row_major);
    __syncthreads();

    {
        const int row = tid >> 1, c0 = (tid & 1) * 32;
        const float inv = 1.0f / lsum[row];
        const int b = bh >> 4, h = bh & 15;
        const size_t gbase = ((size_t)(b*Ss_ + qt*64 + row)) * Dd_ + h*64 + c0;
        #pragma unroll
        for (int c = 0; c < 32; c += 4) {
            __nv_bfloat16 hh[4], ll[4];
            #pragma unroll
            for (int j = 0; j < 4; j++)
                split_bf16(Sst[row*68 + c0 + c + j] * inv, hh[j], ll[j]);
            *(uint2*)&P_AOH[gbase + c] = *(uint2*)hh;
            *(uint2*)&P_AOL[gbase + c] = *(uint2*)ll;
        }
    }
}

// ---------------------------------------------------------------------------
extern "C" void kernel_launch(void* const* d_in, const int* in_sizes, int n_in,
                              void* d_out, int out_size)
{
    const float* x     = (const float*)d_in[0];
    const float* W_qkv = (const float*)d_in[1];
    const float* b_qkv = (const float*)d_in[2];
    const float* W_out = (const float*)d_in[3];
    const float* b_out = (const float*)d_in[4];
    float* out = (float*)d_out;

    cudaFuncSetAttribute(attn_wmma,
        cudaFuncAttributeMaxDynamicSharedMemorySize, AT_SMEM);
    cudaFuncSetAttribute(gemm_bf16x3<0>,
        cudaFuncAttributeMaxDynamicSharedMemorySize, GEMM_SMEM);
    cudaFuncSetAttribute(gemm_bf16x3<1>,
        cudaFuncAttributeMaxDynamicSharedMemorySize, GEMM_SMEM);

    split_x<<<Mm_*Dd_/1024, 256>>>(x, Mm_*Dd_);
    transpose_split<0><<<dim3(NQKV_/32, Dd_/32), dim3(32,8)>>>(W_qkv, Dd_, NQKV_);
    transpose_split<1><<<dim3(Dd_/32,  Dd_/32), dim3(32,8)>>>(W_out, Dd_, Dd_);

    gemm_bf16x3<0><<<dim3(NQKV_/128, Mm_/128), 512, GEMM_SMEM>>>(b_qkv, nullptr);

    attn_wmma<<<dim3(Ss_/64, Bb_*Hh_), 128, AT_SMEM>>>();

    gemm_bf16x3<1><<<dim3(Dd_/128, Mm_/128), 512, GEMM_SMEM>>>(b_out, out);
}

// round 11
// speedup vs baseline: 1.5961x; 1.5961x over previous
#include <cuda_runtime.h>
#include <cuda_fp16.h>
#include <mma.h>
#include <math.h>
#include <float.h>
#include <stdint.h>

using namespace nvcuda;

#define Bb_ 2
#define Ss_ 2048
#define Dd_ 1024
#define Hh_ 16
#define HD_ 64
#define Mm_ (Bb_*Ss_)      /* 4096 */
#define NQKV_ (3*Dd_)      /* 3072 */

// ---------------------------------------------------------------------------
// Single scratch arena (80 MB decl — proven-safe), fp16 layout:
//   [0,16M)   xh/xl  -> reused as AOh/AOl after attention
//   [16,22M)  Wq^T single fp16   [22,24M) Wo^T single fp16
//   [24,56M)  Qh,Ql,K,V (fp16, [b,h,s,hd], 8MB each)
// ---------------------------------------------------------------------------
#define MB_ (1024*1024)
__device__ __align__(128) unsigned char g_arena[80*MB_];

#define P_XH  ((__half*)(g_arena))
#define P_XL  ((__half*)(g_arena + 8*MB_))
#define P_AOH P_XH
#define P_AOL P_XL
#define P_WQ  ((__half*)(g_arena + 16*MB_))
#define P_WO  ((__half*)(g_arena + 22*MB_))
#define P_QH  ((__half*)(g_arena + 24*MB_))
#define P_QL  ((__half*)(g_arena + 32*MB_))
#define P_KS  ((__half*)(g_arena + 40*MB_))
#define P_VS  ((__half*)(g_arena + 48*MB_))

// ---------------------------------------------------------------------------
// helpers
// ---------------------------------------------------------------------------
__device__ __forceinline__ uint32_t smem_u32(const void* p) {
    uint32_t a;
    asm("{ .reg .u64 t; cvta.to.shared.u64 t, %1; cvt.u32.u64 %0, t; }"
        : "=r"(a) : "l"(p));
    return a;
}
__device__ __forceinline__ void cp16(uint32_t saddr, const void* gaddr) {
    asm volatile("cp.async.cg.shared.global [%0], [%1], 16;"
                 :: "r"(saddr), "l"(gaddr));
}
__device__ __forceinline__ void split_f16(float v, __half& h, __half& l) {
    h = __float2half_rn(v);
    l = __float2half_rn(v - __half2float(h));
}

// ---------------------------------------------------------------------------
// Split x (fp32) -> fp16 hi/lo
// ---------------------------------------------------------------------------
__global__ __launch_bounds__(256) void split_x(const float* __restrict__ in, int n)
{
    __half* oh = P_XH;
    __half* ol = P_XL;
    for (int i = (blockIdx.x * 256 + threadIdx.x) * 4; i < n; i += gridDim.x * 1024) {
        float4 v = *(const float4*)(in + i);
        __half h[4], l[4];
        split_f16(v.x, h[0], l[0]);
        split_f16(v.y, h[1], l[1]);
        split_f16(v.z, h[2], l[2]);
        split_f16(v.w, h[3], l[3]);
        *(uint2*)(oh + i) = *(uint2*)h;
        *(uint2*)(ol + i) = *(uint2*)l;
    }
}

// ---------------------------------------------------------------------------
// Transpose W [R,C] -> single fp16 [C,R] K-major
// ---------------------------------------------------------------------------
template<int WSEL>
__global__ __launch_bounds__(256) void transpose_h(const float* __restrict__ in,
                                                   int R, int C)
{
    __shared__ float t[32][33];
    __half* o = (WSEL == 0) ? P_WQ : P_WO;
    const int c0 = blockIdx.x * 32, r0 = blockIdx.y * 32;
    const int tx = threadIdx.x, ty = threadIdx.y;
    #pragma unroll
    for (int i = 0; i < 32; i += 8)
        t[ty + i][tx] = in[(size_t)(r0 + ty + i) * C + c0 + tx];
    __syncthreads();
    #pragma unroll
    for (int i = 0; i < 32; i += 8)
        o[(size_t)(c0 + ty + i) * R + r0 + tx] = __float2half_rn(t[tx][ty + i]);
}

// ---------------------------------------------------------------------------
// fp16 2-term GEMM: C = (Ah+Al) . B^T, A split hi/lo, B single fp16.
// 512 threads = 16 warps (4x4), warp tile 32x32, BM=BN=128, BK=32,
// cp.async double-buffered.
// MODE 0: A=x, B=Wq^T, epilogue emits Qh/Ql (x0.125), K, V (fp16).
// MODE 1: A=AO, B=Wo^T, writes fp32 Cout + bias.
// ---------------------------------------------------------------------------
#define LDT 40
#define MAT_ELEM (128*LDT)
#define MAT_BYTES (MAT_ELEM*2)                   /* 10240 */
#define STAGE_BYTES (3*MAT_BYTES)                /* 30720 */
#define GEMM_SMEM (2*STAGE_BYTES)                /* 61440 */

template<int MODE>
__global__ __launch_bounds__(512) void gemm_f16x2(
    const float* __restrict__ bias, float* __restrict__ Cout)
{
    extern __shared__ __align__(16) char smem[];
    const uint32_t sbase = smem_u32(smem);
    const int tid = threadIdx.x;
    const int wid = tid >> 5, lane = tid & 31;
    const int warp_m = wid >> 2, warp_n = wid & 3;
    const int cCol = blockIdx.x, cRow = blockIdx.y;
    const int Kd = Dd_;

    const __half* Agh = (MODE == 0) ? P_XH : P_AOH;
    const __half* Agl = (MODE == 0) ? P_XL : P_AOL;
    const __half* Bg  = (MODE == 0) ? P_WQ : P_WO;

    const __half* Ah_g = Agh + (size_t)(cRow * 128) * Kd;
    const __half* Al_g = Agl + (size_t)(cRow * 128) * Kd;
    const __half* B_g  = Bg  + (size_t)(cCol * 128) * Kd;

    wmma::fragment<wmma::accumulator, 16, 16, 16, float> acc[2][2];
    #pragma unroll
    for (int i = 0; i < 2; i++)
        #pragma unroll
        for (int j = 0; j < 2; j++)
            wmma::fill_fragment(acc[i][j], 0.0f);

    // 512 16B-chunks per matrix, 1 chunk/thread/matrix
    auto issue = [&](int kc) {
        const uint32_t sb = sbase + (kc & 1) * STAGE_BYTES;
        const int row = tid >> 2, c4 = tid & 3;
        const size_t go = (size_t)row * Kd + kc * 32 + c4 * 8;
        const uint32_t so = row * (LDT * 2) + c4 * 16;
        cp16(sb + 0*MAT_BYTES + so, Ah_g + go);
        cp16(sb + 1*MAT_BYTES + so, Al_g + go);
        cp16(sb + 2*MAT_BYTES + so, B_g  + go);
        asm volatile("cp.async.commit_group;");
    };

    issue(0);

    for (int kc = 0; kc < Kd / 32; kc++) {
        if (kc + 1 < Kd / 32) issue(kc + 1);
        else asm volatile("cp.async.commit_group;");
        asm volatile("cp.async.wait_group 1;");
        __syncthreads();

        const __half* As_h = (const __half*)(smem + (kc & 1) * STAGE_BYTES);
        const __half* As_l = As_h + MAT_ELEM;
        const __half* Bs   = As_h + 2*MAT_ELEM;

        #pragma unroll
        for (int ks = 0; ks < 32; ks += 16) {
            wmma::fragment<wmma::matrix_a, 16, 16, 16, __half, wmma::row_major> ah[2], al[2];
            #pragma unroll
            for (int i = 0; i < 2; i++) {
                const int r = warp_m*32 + i*16;
                wmma::load_matrix_sync(ah[i], &As_h[r*LDT + ks], LDT);
                wmma::load_matrix_sync(al[i], &As_l[r*LDT + ks], LDT);
            }
            #pragma unroll
            for (int j = 0; j < 2; j++) {
                const int n = warp_n*32 + j*16;
                wmma::fragment<wmma::matrix_b, 16, 16, 16, __half, wmma::col_major> bf;
                wmma::load_matrix_sync(bf, &Bs[n*LDT + ks], LDT);
                #pragma unroll
                for (int i = 0; i < 2; i++) {
                    wmma::mma_sync(acc[i][j], ah[i], bf, acc[i][j]);
                    wmma::mma_sync(acc[i][j], al[i], bf, acc[i][j]);
                }
            }
        }
        __syncthreads();
    }

    // epilogue via per-warp smem patch
    float* patch = (float*)smem + wid * 256;
    #pragma unroll
    for (int i = 0; i < 2; i++) {
        #pragma unroll
        for (int j = 0; j < 2; j++) {
            wmma::store_matrix_sync(patch, acc[i][j], 16, wmma::mem_row_major);
            __syncwarp();
            const int m0 = cRow*128 + warp_m*32 + i*16;
            const int n0 = cCol*128 + warp_n*32 + j*16;
            #pragma unroll
            for (int e = 0; e < 8; e++) {
                const int idx = lane*8 + e;
                const int r = idx >> 4, cn = idx & 15;
                const int m = m0 + r, n = n0 + cn;
                const float val = patch[idx] + bias[n];
                if (MODE == 1) {
                    Cout[(size_t)m * Dd_ + n] = val;
                } else {
                    const int b = m >> 11, sq = m & (Ss_ - 1);
                    const int h = n / 192;
                    const int c = n - h * 192;
                    const size_t base = ((size_t)(b * Hh_ + h) * Ss_ + sq) * HD_;
                    if (c < 64) {
                        __half hh, ll;
                        split_f16(val * 0.125f, hh, ll);   // fold 1/sqrt(hd)
                        P_QH[base + c] = hh; P_QL[base + c] = ll;
                    } else if (c < 128) {
                        P_KS[base + c - 64] = __float2half_rn(val);
                    } else {
                        P_VS[base + c - 128] = __float2half_rn(val);
                    }
                }
            }
            __syncwarp();
        }
    }
}

// ---------------------------------------------------------------------------
// fp16 2-term causal attention, unnormalized softmax (round-9 structure).
// S = (Qh+Ql).K^T (K single); P split hi/lo; O' = (Ph+Pl).V (V single).
// 128 threads = 4 warps; smem 73 KB -> 3 CTAs/SM.
// ---------------------------------------------------------------------------
#define O_SST 0
#define O_QHs 17408
#define O_QLs 26624
#define O_KSs 35840
#define O_VSs 45056
#define O_PHs 54272
#define O_PLs 63488
#define O_LS  72704
#define AT_SMEM 72960

__global__ __launch_bounds__(128) void attn_wmma()
{
    extern __shared__ __align__(16) char sm[];
    const uint32_t sb = smem_u32(sm);
    float* Sst = (float*)(sm + O_SST);
    __half* Qh = (__half*)(sm + O_QHs);
    __half* Ql = (__half*)(sm + O_QLs);
    __half* Ks = (__half*)(sm + O_KSs);
    __half* Vs = (__half*)(sm + O_VSs);
    __half* Ph = (__half*)(sm + O_PHs);
    __half* Pl = (__half*)(sm + O_PLs);
    float* lsum = (float*)(sm + O_LS);

    const int tid = threadIdx.x;
    const int wid = tid >> 5;
    const int qt  = blockIdx.x;
    const int bh  = blockIdx.y;

    {
        const __half* QHg = P_QH + ((size_t)bh * Ss_ + qt*64) * HD_;
        const __half* QLg = P_QL + ((size_t)bh * Ss_ + qt*64) * HD_;
        #pragma unroll
        for (int i = 0; i < 4; i++) {
            const int idx = tid + i*128;
            const int row = idx >> 3, c8 = idx & 7;
            const uint32_t so = row*144 + c8*16;
            const int go = row*64 + c8*8;
            cp16(sb + O_QHs + so, QHg + go);
            cp16(sb + O_QLs + so, QLg + go);
        }
        asm volatile("cp.async.commit_group;");
    }
    if (tid < 64) lsum[tid] = 0.f;

    wmma::fragment<wmma::accumulator, 16, 16, 16, float> accO[4];
    #pragma unroll
    for (int n = 0; n < 4; n++) wmma::fill_fragment(accO[n], 0.0f);

    const int r0 = wid * 16;

    for (int kt = 0; kt <= qt; kt++) {
        {
            const size_t gb = ((size_t)bh * Ss_ + kt*64) * HD_;
            const __half* KHg = P_KS + gb;
            const __half* VHg = P_VS + gb;
            #pragma unroll
            for (int i = 0; i < 4; i++) {
                const int idx = tid + i*128;
                const int row = idx >> 3, c8 = idx & 7;
                const uint32_t so = row*144 + c8*16;
                const int go = row*64 + c8*8;
                cp16(sb + O_KSs + so, KHg + go);
                cp16(sb + O_VSs + so, VHg + go);
            }
            asm volatile("cp.async.commit_group;");
        }
        asm volatile("cp.async.wait_group 0;");
        __syncthreads();

        // S = (Qh+Ql) . K^T
        wmma::fragment<wmma::accumulator, 16, 16, 16, float> accS[4];
        #pragma unroll
        for (int n = 0; n < 4; n++) wmma::fill_fragment(accS[n], 0.0f);
        #pragma unroll
        for (int k0 = 0; k0 < 64; k0 += 16) {
            wmma::fragment<wmma::matrix_a, 16, 16, 16, __half, wmma::row_major> ah, al;
            wmma::load_matrix_sync(ah, &Qh[r0*72 + k0], 72);
            wmma::load_matrix_sync(al, &Ql[r0*72 + k0], 72);
            #pragma unroll
            for (int n = 0; n < 4; n++) {
                wmma::fragment<wmma::matrix_b, 16, 16, 16, __half, wmma::col_major> bf;
                wmma::load_matrix_sync(bf, &Ks[(n*16)*72 + k0], 72);
                wmma::mma_sync(accS[n], ah, bf, accS[n]);
                wmma::mma_sync(accS[n], al, bf, accS[n]);
            }
        }
        #pragma unroll
        for (int n = 0; n < 4; n++)
            wmma::store_matrix_sync(&Sst[r0*68 + n*16], accS[n], 68, wmma::mem_row_major);
        __syncthreads();

        // exp + row sums + P split
        {
            const int row = tid >> 1, c0 = (tid & 1) * 32;
            const bool diag = (kt == qt);
            float partial = 0.f;
            #pragma unroll 8
            for (int c = 0; c < 32; c++) {
                const int col = c0 + c;
                const float s = Sst[row*68 + col];
                const float p = (!diag || col <= row) ? __expf(s) : 0.f;
                partial += p;
                __half hh, ll;
                split_f16(p, hh, ll);
                Ph[row*72 + col] = hh;
                Pl[row*72 + col] = ll;
            }
            const float other = __shfl_xor_sync(0xffffffffu, partial, 1);
            if (!(tid & 1)) lsum[row] += partial + other;
        }
        __syncthreads();

        // O' += (Ph+Pl) . V
        #pragma unroll
        for (int k0 = 0; k0 < 64; k0 += 16) {
            wmma::fragment<wmma::matrix_a, 16, 16, 16, __half, wmma::row_major> pa, pal;
            wmma::load_matrix_sync(pa,  &Ph[r0*72 + k0], 72);
            wmma::load_matrix_sync(pal, &Pl[r0*72 + k0], 72);
            #pragma unroll
            for (int n = 0; n < 4; n++) {
                wmma::fragment<wmma::matrix_b, 16, 16, 16, __half, wmma::row_major> vb;
                wmma::load_matrix_sync(vb, &Vs[k0*72 + n*16], 72);
                wmma::mma_sync(accO[n], pa,  vb, accO[n]);
                wmma::mma_sync(accO[n], pal, vb, accO[n]);
            }
        }
        __syncthreads();
    }

    // final: store O', normalize, split to fp16 hi/lo AO
    #pragma unroll
    for (int n = 0; n < 4; n++)
        wmma::store_matrix_sync(&Sst[r0*68 + n*16], accO[n], 68, wmma::mem_row_major);
    __syncthreads();

    {
        const int row = tid >> 1, c0 = (tid & 1) * 32;
        const float inv = 1.0f / lsum[row];
        const int b = bh >> 4, h = bh & 15;
        const size_t gbase = ((size_t)(b*Ss_ + qt*64 + row)) * Dd_ + h*64 + c0;
        #pragma unroll
        for (int c = 0; c < 32; c += 4) {
            __half hh[4], ll[4];
            #pragma unroll
            for (int j = 0; j < 4; j++)
                split_f16(Sst[row*68 + c0 + c + j] * inv, hh[j], ll[j]);
            *(uint2*)&P_AOH[gbase + c] = *(uint2*)hh;
            *(uint2*)&P_AOL[gbase + c] = *(uint2*)ll;
        }
    }
}

// ---------------------------------------------------------------------------
extern "C" void kernel_launch(void* const* d_in, const int* in_sizes, int n_in,
                              void* d_out, int out_size)
{
    const float* x     = (const float*)d_in[0];
    const float* W_qkv = (const float*)d_in[1];
    const float* b_qkv = (const float*)d_in[2];
    const float* W_out = (const float*)d_in[3];
    const float* b_out = (const float*)d_in[4];
    float* out = (float*)d_out;

    cudaFuncSetAttribute(attn_wmma,
        cudaFuncAttributeMaxDynamicSharedMemorySize, AT_SMEM);
    cudaFuncSetAttribute(gemm_f16x2<0>,
        cudaFuncAttributeMaxDynamicSharedMemorySize, GEMM_SMEM);
    cudaFuncSetAttribute(gemm_f16x2<1>,
        cudaFuncAttributeMaxDynamicSharedMemorySize, GEMM_SMEM);

    split_x<<<Mm_*Dd_/1024, 256>>>(x, Mm_*Dd_);
    transpose_h<0><<<dim3(NQKV_/32, Dd_/32), dim3(32,8)>>>(W_qkv, Dd_, NQKV_);
    transpose_h<1><<<dim3(Dd_/32,  Dd_/32), dim3(32,8)>>>(W_out, Dd_, Dd_);

    gemm_f16x2<0><<<dim3(NQKV_/128, Mm_/128), 512, GEMM_SMEM>>>(b_qkv, nullptr);

    attn_wmma<<<dim3(Ss_/64, Bb_*Hh_), 128, AT_SMEM>>>();

    gemm_f16x2<1><<<dim3(Dd_/128, Mm_/128), 512, GEMM_SMEM>>>(b_out, out);
}

// round 12
// speedup vs baseline: 1.8257x; 1.1438x over previous
#include <cuda_runtime.h>
#include <cuda_fp16.h>
#include <mma.h>
#include <math.h>
#include <float.h>
#include <stdint.h>

using namespace nvcuda;

#define Bb_ 2
#define Ss_ 2048
#define Dd_ 1024
#define Hh_ 16
#define HD_ 64
#define Mm_ (Bb_*Ss_)      /* 4096 */
#define NQKV_ (3*Dd_)      /* 3072 */

// ---------------------------------------------------------------------------
// Single scratch arena (80 MB decl — proven-safe), fp16 layout:
//   [0,16M)   xh/xl  -> reused as AOh/AOl after attention
//   [16,22M)  Wq^T single fp16   [22,24M) Wo^T single fp16
//   [24,56M)  Qh,Ql,K,V (fp16, [b,h,s,hd], 8MB each)
// ---------------------------------------------------------------------------
#define MB_ (1024*1024)
__device__ __align__(128) unsigned char g_arena[80*MB_];

#define P_XH  ((__half*)(g_arena))
#define P_XL  ((__half*)(g_arena + 8*MB_))
#define P_AOH P_XH
#define P_AOL P_XL
#define P_WQ  ((__half*)(g_arena + 16*MB_))
#define P_WO  ((__half*)(g_arena + 22*MB_))
#define P_QH  ((__half*)(g_arena + 24*MB_))
#define P_QL  ((__half*)(g_arena + 32*MB_))
#define P_KS  ((__half*)(g_arena + 40*MB_))
#define P_VS  ((__half*)(g_arena + 48*MB_))

// ---------------------------------------------------------------------------
// helpers
// ---------------------------------------------------------------------------
__device__ __forceinline__ uint32_t smem_u32(const void* p) {
    uint32_t a;
    asm("{ .reg .u64 t; cvta.to.shared.u64 t, %1; cvt.u32.u64 %0, t; }"
        : "=r"(a) : "l"(p));
    return a;
}
__device__ __forceinline__ void cp16(uint32_t saddr, const void* gaddr) {
    asm volatile("cp.async.cg.shared.global [%0], [%1], 16;"
                 :: "r"(saddr), "l"(gaddr));
}
__device__ __forceinline__ void split_f16(float v, __half& h, __half& l) {
    h = __float2half_rn(v);
    l = __float2half_rn(v - __half2float(h));
}

// ---------------------------------------------------------------------------
// Split x (fp32) -> fp16 hi/lo
// ---------------------------------------------------------------------------
__global__ __launch_bounds__(256) void split_x(const float* __restrict__ in, int n)
{
    __half* oh = P_XH;
    __half* ol = P_XL;
    for (int i = (blockIdx.x * 256 + threadIdx.x) * 4; i < n; i += gridDim.x * 1024) {
        float4 v = *(const float4*)(in + i);
        __half h[4], l[4];
        split_f16(v.x, h[0], l[0]);
        split_f16(v.y, h[1], l[1]);
        split_f16(v.z, h[2], l[2]);
        split_f16(v.w, h[3], l[3]);
        *(uint2*)(oh + i) = *(uint2*)h;
        *(uint2*)(ol + i) = *(uint2*)l;
    }
}

// ---------------------------------------------------------------------------
// Transpose W [R,C] -> single fp16 [C,R] K-major
// ---------------------------------------------------------------------------
template<int WSEL>
__global__ __launch_bounds__(256) void transpose_h(const float* __restrict__ in,
                                                   int R, int C)
{
    __shared__ float t[32][33];
    __half* o = (WSEL == 0) ? P_WQ : P_WO;
    const int c0 = blockIdx.x * 32, r0 = blockIdx.y * 32;
    const int tx = threadIdx.x, ty = threadIdx.y;
    #pragma unroll
    for (int i = 0; i < 32; i += 8)
        t[ty + i][tx] = in[(size_t)(r0 + ty + i) * C + c0 + tx];
    __syncthreads();
    #pragma unroll
    for (int i = 0; i < 32; i += 8)
        o[(size_t)(c0 + ty + i) * R + r0 + tx] = __float2half_rn(t[tx][ty + i]);
}

// ---------------------------------------------------------------------------
// fp16 2-term GEMM, small-CTA config: BM=64, BN=128, BK=32.
// 128 threads = 4 warps (2x2), warp tile 32x64, 4 CTAs/SM (independent
// barrier domains — the attention kernel's demonstrated-faster shape).
// MODE 0: A=x, B=Wq^T, epilogue emits Qh/Ql (x0.125), K, V (fp16).
// MODE 1: A=AO, B=Wo^T, writes fp32 Cout + bias.
// ---------------------------------------------------------------------------
#define LDT 40
#define A_ELEM (64*LDT)                          /* 2560 */
#define A_BYTES (A_ELEM*2)                       /* 5120 */
#define B_ELEM (128*LDT)                         /* 5120 */
#define B_BYTES (B_ELEM*2)                       /* 10240 */
#define STAGE_BYTES (2*A_BYTES + B_BYTES)        /* 20480 */
#define GEMM_SMEM (2*STAGE_BYTES)                /* 40960 */

template<int MODE>
__global__ __launch_bounds__(128, 4) void gemm_f16x2(
    const float* __restrict__ bias, float* __restrict__ Cout)
{
    extern __shared__ __align__(16) char smem[];
    const uint32_t sbase = smem_u32(smem);
    const int tid = threadIdx.x;
    const int wid = tid >> 5, lane = tid & 31;
    const int warp_m = wid >> 1, warp_n = wid & 1;   // 2x2 warps, 32x64 tiles
    const int cCol = blockIdx.x, cRow = blockIdx.y;
    const int Kd = Dd_;

    const __half* Agh = (MODE == 0) ? P_XH : P_AOH;
    const __half* Agl = (MODE == 0) ? P_XL : P_AOL;
    const __half* Bg  = (MODE == 0) ? P_WQ : P_WO;

    const __half* Ah_g = Agh + (size_t)(cRow * 64) * Kd;
    const __half* Al_g = Agl + (size_t)(cRow * 64) * Kd;
    const __half* B_g  = Bg  + (size_t)(cCol * 128) * Kd;

    wmma::fragment<wmma::accumulator, 16, 16, 16, float> acc[2][4];
    #pragma unroll
    for (int i = 0; i < 2; i++)
        #pragma unroll
        for (int j = 0; j < 4; j++)
            wmma::fill_fragment(acc[i][j], 0.0f);

    // stage: Ah 256 chunks, Al 256 chunks, B 512 chunks (16B each);
    // 128 threads x 8 chunks: i<2 -> Ah, i<4 -> Al, i<8 -> B.
    auto issue = [&](int kc) {
        const uint32_t sb = sbase + (kc & 1) * STAGE_BYTES;
        #pragma unroll
        for (int i = 0; i < 2; i++) {
            const int ch = tid + i*128;            // 0..255
            const int row = ch >> 2, c4 = ch & 3;
            cp16(sb + row*(LDT*2) + c4*16,
                 Ah_g + (size_t)row * Kd + kc*32 + c4*8);
        }
        #pragma unroll
        for (int i = 0; i < 2; i++) {
            const int ch = tid + i*128;
            const int row = ch >> 2, c4 = ch & 3;
            cp16(sb + A_BYTES + row*(LDT*2) + c4*16,
                 Al_g + (size_t)row * Kd + kc*32 + c4*8);
        }
        #pragma unroll
        for (int i = 0; i < 4; i++) {
            const int ch = tid + i*128;            // 0..511
            const int row = ch >> 2, c4 = ch & 3;
            cp16(sb + 2*A_BYTES + row*(LDT*2) + c4*16,
                 B_g + (size_t)row * Kd + kc*32 + c4*8);
        }
        asm volatile("cp.async.commit_group;");
    };

    issue(0);

    for (int kc = 0; kc < Kd / 32; kc++) {
        if (kc + 1 < Kd / 32) issue(kc + 1);
        else asm volatile("cp.async.commit_group;");
        asm volatile("cp.async.wait_group 1;");
        __syncthreads();

        const __half* As_h = (const __half*)(smem + (kc & 1) * STAGE_BYTES);
        const __half* As_l = As_h + A_ELEM;
        const __half* Bs   = As_h + 2*A_ELEM;

        #pragma unroll
        for (int ks = 0; ks < 32; ks += 16) {
            wmma::fragment<wmma::matrix_a, 16, 16, 16, __half, wmma::row_major> ah[2], al[2];
            #pragma unroll
            for (int i = 0; i < 2; i++) {
                const int r = warp_m*32 + i*16;
                wmma::load_matrix_sync(ah[i], &As_h[r*LDT + ks], LDT);
                wmma::load_matrix_sync(al[i], &As_l[r*LDT + ks], LDT);
            }
            #pragma unroll
            for (int j = 0; j < 4; j++) {
                const int n = warp_n*64 + j*16;
                wmma::fragment<wmma::matrix_b, 16, 16, 16, __half, wmma::col_major> bf;
                wmma::load_matrix_sync(bf, &Bs[n*LDT + ks], LDT);
                #pragma unroll
                for (int i = 0; i < 2; i++) {
                    wmma::mma_sync(acc[i][j], ah[i], bf, acc[i][j]);
                    wmma::mma_sync(acc[i][j], al[i], bf, acc[i][j]);
                }
            }
        }
        __syncthreads();
    }

    // epilogue via per-warp smem patch
    float* patch = (float*)smem + wid * 256;
    #pragma unroll
    for (int i = 0; i < 2; i++) {
        #pragma unroll
        for (int j = 0; j < 4; j++) {
            wmma::store_matrix_sync(patch, acc[i][j], 16, wmma::mem_row_major);
            __syncwarp();
            const int m0 = cRow*64 + warp_m*32 + i*16;
            const int n0 = cCol*128 + warp_n*64 + j*16;
            #pragma unroll
            for (int e = 0; e < 8; e++) {
                const int idx = lane*8 + e;
                const int r = idx >> 4, cn = idx & 15;
                const int m = m0 + r, n = n0 + cn;
                const float val = patch[idx] + bias[n];
                if (MODE == 1) {
                    Cout[(size_t)m * Dd_ + n] = val;
                } else {
                    const int b = m >> 11, sq = m & (Ss_ - 1);
                    const int h = n / 192;
                    const int c = n - h * 192;
                    const size_t base = ((size_t)(b * Hh_ + h) * Ss_ + sq) * HD_;
                    if (c < 64) {
                        __half hh, ll;
                        split_f16(val * 0.125f, hh, ll);   // fold 1/sqrt(hd)
                        P_QH[base + c] = hh; P_QL[base + c] = ll;
                    } else if (c < 128) {
                        P_KS[base + c - 64] = __float2half_rn(val);
                    } else {
                        P_VS[base + c - 128] = __float2half_rn(val);
                    }
                }
            }
            __syncwarp();
        }
    }
}

// ---------------------------------------------------------------------------
// fp16 2-term causal attention, unnormalized softmax (proven round-11).
// ---------------------------------------------------------------------------
#define O_SST 0
#define O_QHs 17408
#define O_QLs 26624
#define O_KSs 35840
#define O_VSs 45056
#define O_PHs 54272
#define O_PLs 63488
#define O_LS  72704
#define AT_SMEM 72960

__global__ __launch_bounds__(128) void attn_wmma()
{
    extern __shared__ __align__(16) char sm[];
    const uint32_t sb = smem_u32(sm);
    float* Sst = (float*)(sm + O_SST);
    __half* Qh = (__half*)(sm + O_QHs);
    __half* Ql = (__half*)(sm + O_QLs);
    __half* Ks = (__half*)(sm + O_KSs);
    __half* Vs = (__half*)(sm + O_VSs);
    __half* Ph = (__half*)(sm + O_PHs);
    __half* Pl = (__half*)(sm + O_PLs);
    float* lsum = (float*)(sm + O_LS);

    const int tid = threadIdx.x;
    const int wid = tid >> 5;
    const int qt  = blockIdx.x;
    const int bh  = blockIdx.y;

    {
        const __half* QHg = P_QH + ((size_t)bh * Ss_ + qt*64) * HD_;
        const __half* QLg = P_QL + ((size_t)bh * Ss_ + qt*64) * HD_;
        #pragma unroll
        for (int i = 0; i < 4; i++) {
            const int idx = tid + i*128;
            const int row = idx >> 3, c8 = idx & 7;
            const uint32_t so = row*144 + c8*16;
            const int go = row*64 + c8*8;
            cp16(sb + O_QHs + so, QHg + go);
            cp16(sb + O_QLs + so, QLg + go);
        }
        asm volatile("cp.async.commit_group;");
    }
    if (tid < 64) lsum[tid] = 0.f;

    wmma::fragment<wmma::accumulator, 16, 16, 16, float> accO[4];
    #pragma unroll
    for (int n = 0; n < 4; n++) wmma::fill_fragment(accO[n], 0.0f);

    const int r0 = wid * 16;

    for (int kt = 0; kt <= qt; kt++) {
        {
            const size_t gb = ((size_t)bh * Ss_ + kt*64) * HD_;
            const __half* KHg = P_KS + gb;
            const __half* VHg = P_VS + gb;
            #pragma unroll
            for (int i = 0; i < 4; i++) {
                const int idx = tid + i*128;
                const int row = idx >> 3, c8 = idx & 7;
                const uint32_t so = row*144 + c8*16;
                const int go = row*64 + c8*8;
                cp16(sb + O_KSs + so, KHg + go);
                cp16(sb + O_VSs + so, VHg + go);
            }
            asm volatile("cp.async.commit_group;");
        }
        asm volatile("cp.async.wait_group 0;");
        __syncthreads();

        // S = (Qh+Ql) . K^T
        wmma::fragment<wmma::accumulator, 16, 16, 16, float> accS[4];
        #pragma unroll
        for (int n = 0; n < 4; n++) wmma::fill_fragment(accS[n], 0.0f);
        #pragma unroll
        for (int k0 = 0; k0 < 64; k0 += 16) {
            wmma::fragment<wmma::matrix_a, 16, 16, 16, __half, wmma::row_major> ah, al;
            wmma::load_matrix_sync(ah, &Qh[r0*72 + k0], 72);
            wmma::load_matrix_sync(al, &Ql[r0*72 + k0], 72);
            #pragma unroll
            for (int n = 0; n < 4; n++) {
                wmma::fragment<wmma::matrix_b, 16, 16, 16, __half, wmma::col_major> bf;
                wmma::load_matrix_sync(bf, &Ks[(n*16)*72 + k0], 72);
                wmma::mma_sync(accS[n], ah, bf, accS[n]);
                wmma::mma_sync(accS[n], al, bf, accS[n]);
            }
        }
        #pragma unroll
        for (int n = 0; n < 4; n++)
            wmma::store_matrix_sync(&Sst[r0*68 + n*16], accS[n], 68, wmma::mem_row_major);
        __syncthreads();

        // exp + row sums + P split
        {
            const int row = tid >> 1, c0 = (tid & 1) * 32;
            const bool diag = (kt == qt);
            float partial = 0.f;
            #pragma unroll 8
            for (int c = 0; c < 32; c++) {
                const int col = c0 + c;
                const float s = Sst[row*68 + col];
                const float p = (!diag || col <= row) ? __expf(s) : 0.f;
                partial += p;
                __half hh, ll;
                split_f16(p, hh, ll);
                Ph[row*72 + col] = hh;
                Pl[row*72 + col] = ll;
            }
            const float other = __shfl_xor_sync(0xffffffffu, partial, 1);
            if (!(tid & 1)) lsum[row] += partial + other;
        }
        __syncthreads();

        // O' += (Ph+Pl) . V
        #pragma unroll
        for (int k0 = 0; k0 < 64; k0 += 16) {
            wmma::fragment<wmma::matrix_a, 16, 16, 16, __half, wmma::row_major> pa, pal;
            wmma::load_matrix_sync(pa,  &Ph[r0*72 + k0], 72);
            wmma::load_matrix_sync(pal, &Pl[r0*72 + k0], 72);
            #pragma unroll
            for (int n = 0; n < 4; n++) {
                wmma::fragment<wmma::matrix_b, 16, 16, 16, __half, wmma::row_major> vb;
                wmma::load_matrix_sync(vb, &Vs[k0*72 + n*16], 72);
                wmma::mma_sync(accO[n], pa,  vb, accO[n]);
                wmma::mma_sync(accO[n], pal, vb, accO[n]);
            }
        }
        __syncthreads();
    }

    // final: store O', normalize, split to fp16 hi/lo AO
    #pragma unroll
    for (int n = 0; n < 4; n++)
        wmma::store_matrix_sync(&Sst[r0*68 + n*16], accO[n], 68, wmma::mem_row_major);
    __syncthreads();

    {
        const int row = tid >> 1, c0 = (tid & 1) * 32;
        const float inv = 1.0f / lsum[row];
        const int b = bh >> 4, h = bh & 15;
        const size_t gbase = ((size_t)(b*Ss_ + qt*64 + row)) * Dd_ + h*64 + c0;
        #pragma unroll
        for (int c = 0; c < 32; c += 4) {
            __half hh[4], ll[4];
            #pragma unroll
            for (int j = 0; j < 4; j++)
                split_f16(Sst[row*68 + c0 + c + j] * inv, hh[j], ll[j]);
            *(uint2*)&P_AOH[gbase + c] = *(uint2*)hh;
            *(uint2*)&P_AOL[gbase + c] = *(uint2*)ll;
        }
    }
}

// ---------------------------------------------------------------------------
extern "C" void kernel_launch(void* const* d_in, const int* in_sizes, int n_in,
                              void* d_out, int out_size)
{
    const float* x     = (const float*)d_in[0];
    const float* W_qkv = (const float*)d_in[1];
    const float* b_qkv = (const float*)d_in[2];
    const float* W_out = (const float*)d_in[3];
    const float* b_out = (const float*)d_in[4];
    float* out = (float*)d_out;

    cudaFuncSetAttribute(attn_wmma,
        cudaFuncAttributeMaxDynamicSharedMemorySize, AT_SMEM);
    cudaFuncSetAttribute(gemm_f16x2<0>,
        cudaFuncAttributeMaxDynamicSharedMemorySize, GEMM_SMEM);
    cudaFuncSetAttribute(gemm_f16x2<1>,
        cudaFuncAttributeMaxDynamicSharedMemorySize, GEMM_SMEM);

    split_x<<<Mm_*Dd_/1024, 256>>>(x, Mm_*Dd_);
    transpose_h<0><<<dim3(NQKV_/32, Dd_/32), dim3(32,8)>>>(W_qkv, Dd_, NQKV_);
    transpose_h<1><<<dim3(Dd_/32,  Dd_/32), dim3(32,8)>>>(W_out, Dd_, Dd_);

    gemm_f16x2<0><<<dim3(NQKV_/128, Mm_/64), 128, GEMM_SMEM>>>(b_qkv, nullptr);

    attn_wmma<<<dim3(Ss_/64, Bb_*Hh_), 128, AT_SMEM>>>();

    gemm_f16x2<1><<<dim3(Dd_/128, Mm_/64), 128, GEMM_SMEM>>>(b_out, out);
}